// round 6
// baseline (speedup 1.0000x reference)
#include <cuda_runtime.h>

#define STRIDE   10
#define NF       128
#define PAIRS    8128      // 128*127/2
#define NTASKS   20        // 16-row blocks x 32-col chunks covering lower triangle
#define THREADS  320       // 10 warps x 2 tasks each

// task -> (16-row block index, 32-col chunk index)
__constant__ unsigned char c_bi8[NTASKS] = {0,1,2,2,3,3,4,4,4,5,5,5,6,6,6,6,7,7,7,7};
__constant__ unsigned char c_jc [NTASKS] = {0,0,0,1,0,1,0,1,2,0,1,2,0,1,2,3,0,1,2,3};

__global__ __launch_bounds__(THREADS, 5)   // cap regs at 40 -> 5 CTAs/SM
void corr_win_kernel(const float* __restrict__ x, float* __restrict__ out)
{
    __shared__ float ms[STRIDE][NF];   // normalized columns: (x-mean)/||x-mean||

    const int w    = blockIdx.x;       // window = b*100 + l
    const int tid  = threadIdx.x;
    const int warp = tid >> 5;
    const int lane = tid & 31;
    const float* __restrict__ xw = x + (size_t)w * (STRIDE * NF);

    // ---- Phase 1: load column, center, scale by 1/||.||, store to smem ---
    if (tid < NF) {
        float v[STRIDE];
        #pragma unroll
        for (int s = 0; s < STRIDE; ++s) v[s] = __ldcs(&xw[s * NF + tid]);
        float sum = 0.f;
        #pragma unroll
        for (int s = 0; s < STRIDE; ++s) sum += v[s];
        const float mean = sum * (1.0f / STRIDE);
        float s2 = 0.f;
        #pragma unroll
        for (int s = 0; s < STRIDE; ++s) {
            v[s] -= mean;
            s2 = fmaf(v[s], v[s], s2);
        }
        const float invn = (s2 > 0.f) ? rsqrtf(s2) : 0.f;  // divide_no_nan
        #pragma unroll
        for (int s = 0; s < STRIDE; ++s) ms[s][tid] = v[s] * invn;
    }
    __syncthreads();

    float* __restrict__ ow = out + (size_t)w * PAIRS;

    // ---- Phase 2: two warp-tasks per warp, 16x32 tile each ---------------
    #pragma unroll
    for (int k = 0; k < 2; ++k) {
        const int t  = warp * 2 + k;
        const int i0 = (int)c_bi8[t] * 16;
        const int j  = (int)c_jc[t] * 32 + lane;   // coalesced column

        float acc[16];
        #pragma unroll
        for (int u = 0; u < 16; ++u) acc[u] = 0.f;

        #pragma unroll
        for (int s = 0; s < STRIDE; ++s) {
            const float b = ms[s][j];              // coalesced, 1 wavefront
            // interleave each broadcast A-quad with its FMA group
            // (keeps live set to 16 acc + one float4 stage)
            #pragma unroll
            for (int q = 0; q < 4; ++q) {
                const float4 A = *(const float4*)&ms[s][i0 + 4 * q];
                acc[4*q+0] = fmaf(A.x, b, acc[4*q+0]);
                acc[4*q+1] = fmaf(A.y, b, acc[4*q+1]);
                acc[4*q+2] = fmaf(A.z, b, acc[4*q+2]);
                acc[4*q+3] = fmaf(A.w, b, acc[4*q+3]);
            }
        }

        // direct coalesced predicated stores (row i = consecutive tri idx)
        #pragma unroll
        for (int u = 0; u < 16; ++u) {
            const int i = i0 + u;
            if (j < i)
                __stcs(&ow[(i * (i - 1)) / 2 + j], acc[u]);
        }
    }
}

extern "C" void kernel_launch(void* const* d_in, const int* in_sizes, int n_in,
                              void* d_out, int out_size)
{
    const float* x = (const float*)d_in[0];
    float* out     = (float*)d_out;
    int n_windows  = in_sizes[0] / (STRIDE * NF);   // 6400
    corr_win_kernel<<<n_windows, THREADS>>>(x, out);
}

// round 7
// speedup vs baseline: 1.1699x; 1.1699x over previous
#include <cuda_runtime.h>

#define STRIDE   10
#define NF       128
#define PAIRS    8128      // 128*127/2
#define NTASKS   20        // 16-row blocks x 32-col chunks covering lower triangle
#define THREADS  320       // 10 warps x 2 tasks each

// task -> (16-row block index, 32-col chunk index)
__constant__ unsigned char c_bi8[NTASKS] = {0,1,2,2,3,3,4,4,4,5,5,5,6,6,6,6,7,7,7,7};
__constant__ unsigned char c_jc [NTASKS] = {0,0,0,1,0,1,0,1,2,0,1,2,0,1,2,3,0,1,2,3};

__global__ __launch_bounds__(THREADS, 4)   // cap 51 regs: 4 CTAs/SM, no spills
void corr_win_kernel(const float* __restrict__ x, float* __restrict__ out)
{
    __shared__ float ms[STRIDE][NF];   // normalized columns: (x-mean)/||x-mean||

    const int w    = blockIdx.x;       // window = b*100 + l
    const int tid  = threadIdx.x;
    const int warp = tid >> 5;
    const int lane = tid & 31;
    const float* __restrict__ xw = x + (size_t)w * (STRIDE * NF);

    // ---- Phase 1: load column, center, scale by 1/||.||, store to smem ---
    if (tid < NF) {
        float v[STRIDE];
        #pragma unroll
        for (int s = 0; s < STRIDE; ++s) v[s] = __ldcs(&xw[s * NF + tid]);
        float sum = 0.f;
        #pragma unroll
        for (int s = 0; s < STRIDE; ++s) sum += v[s];
        const float mean = sum * (1.0f / STRIDE);
        float s2 = 0.f;
        #pragma unroll
        for (int s = 0; s < STRIDE; ++s) {
            v[s] -= mean;
            s2 = fmaf(v[s], v[s], s2);
        }
        const float invn = (s2 > 0.f) ? rsqrtf(s2) : 0.f;  // divide_no_nan
        #pragma unroll
        for (int s = 0; s < STRIDE; ++s) ms[s][tid] = v[s] * invn;
    }
    __syncthreads();

    float* __restrict__ ow = out + (size_t)w * PAIRS;

    // ---- Phase 2: two warp-tasks per warp, 16x32 tile, packed f32x2 FMAs --
    #pragma unroll
    for (int k = 0; k < 2; ++k) {
        const int t  = warp * 2 + k;
        const int i0 = (int)c_bi8[t] * 16;
        const int jb = (int)c_jc [t] * 32;
        const int j  = jb + lane;                 // coalesced column

        // 8 packed accumulators = 16 rows, paired (i, i+1)
        unsigned long long acc[8];
        #pragma unroll
        for (int p = 0; p < 8; ++p) acc[p] = 0ULL;

        #pragma unroll
        for (int s = 0; s < STRIDE; ++s) {
            const float b = ms[s][j];             // coalesced, 1 wavefront
            unsigned long long bb;                // (b, b) packed
            asm("mov.b64 %0, {%1, %1};" : "=l"(bb) : "r"(__float_as_uint(b)));
            #pragma unroll
            for (int q = 0; q < 4; ++q) {
                // broadcast LDS.128 = two row-pair f32x2 operands, no repack
                const ulonglong2 A = *(const ulonglong2*)&ms[s][i0 + 4 * q];
                asm("fma.rn.f32x2 %0, %1, %2, %0;" : "+l"(acc[2*q  ]) : "l"(A.x), "l"(bb));
                asm("fma.rn.f32x2 %0, %1, %2, %0;" : "+l"(acc[2*q+1]) : "l"(A.y), "l"(bb));
            }
        }

        // ---- stores: incremental triangular base, branch full/partial ----
        int i    = i0;
        int base = (i0 * (i0 - 1)) >> 1;          // row base for i0
        if (jb + 32 <= i0) {
            // full tile: every j < i, no predicates
            #pragma unroll
            for (int p = 0; p < 8; ++p) {
                unsigned int lo, hi;
                asm("mov.b64 {%0, %1}, %2;" : "=r"(lo), "=r"(hi) : "l"(acc[p]));
                __stcs(&ow[base + j], __uint_as_float(lo)); base += i; ++i;
                __stcs(&ow[base + j], __uint_as_float(hi)); base += i; ++i;
            }
        } else {
            #pragma unroll
            for (int p = 0; p < 8; ++p) {
                unsigned int lo, hi;
                asm("mov.b64 {%0, %1}, %2;" : "=r"(lo), "=r"(hi) : "l"(acc[p]));
                if (j < i) __stcs(&ow[base + j], __uint_as_float(lo));
                base += i; ++i;
                if (j < i) __stcs(&ow[base + j], __uint_as_float(hi));
                base += i; ++i;
            }
        }
    }
}

extern "C" void kernel_launch(void* const* d_in, const int* in_sizes, int n_in,
                              void* d_out, int out_size)
{
    const float* x = (const float*)d_in[0];
    float* out     = (float*)d_out;
    int n_windows  = in_sizes[0] / (STRIDE * NF);   // 6400
    corr_win_kernel<<<n_windows, THREADS>>>(x, out);
}